// round 15
// baseline (speedup 1.0000x reference)
#include <cuda_runtime.h>
#include <cuda_bf16.h>
#include <cstdint>

#define NPL    16384
#define DEG    16
#define DIM    128
#define NT     512
#define GRIDSZ 148
#define NTILES 256            // 64-row tiles per level

// ---- weight slots in smem (bytes). [N][K] bf16, XOR-16B swizzle ----
#define SW1H  0               // 32KB slot: W1a (levels) or W1i-std (phase0)
#define SW1L  16384
#define SW2AH 32768
#define SW2AL 40960
#define SW3AH 49152
#define SW3AL 65536
#define SWFH  81920           // fused WF = W3a @ W1i  (64x64)
#define SWFL  90112
#define SW2IH 98304
#define SW2IL 106496
#define SW3IH 114688
#define SW3IL 131072
#define WTOT  147456

// ---- smem layout (bytes) ----
#define OFF_AH   147456       // A [64][256B] hi   (prologue: iw1 fp32 scratch, 32KB)
#define OFF_AL   163840
#define OFF_BH   180224       // B [64][128B] hi   (prologue: aw3 fp32 scratch, 32KB)
#define OFF_BL   188416
#define OFF_CH   196608       // C [64][128B] hi
#define OFF_CL   204800
#define OFF_IDX  212992       // src 4KB + mask 4KB
#define OFF_BIAS 221184       // 576 floats
#define SM_TOTAL 223744

__device__ __align__(16) float g_inv[7 * NPL * DIM];
__device__ unsigned g_bars[8];          // zero-initialized at module load

__device__ __forceinline__ float leaky(float v) { return v >= 0.f ? v : 0.01f * v; }

__device__ __forceinline__ void split2(float f0, float f1, uint32_t& hi, uint32_t& lo) {
    asm("cvt.rn.bf16x2.f32 %0, %1, %2;" : "=r"(hi) : "f"(f1), "f"(f0));
    float hf0 = __uint_as_float(hi << 16);
    float hf1 = __uint_as_float(hi & 0xFFFF0000u);
    float r0 = f0 - hf0, r1 = f1 - hf1;
    asm("cvt.rn.bf16x2.f32 %0, %1, %2;" : "=r"(lo) : "f"(r1), "f"(r0));
}

__device__ __forceinline__ uint32_t smem_u32(const void* p) {
    uint32_t a;
    asm("{ .reg .u64 t; cvta.to.shared.u64 t, %1; cvt.u32.u64 %0, t; }" : "=r"(a) : "l"(p));
    return a;
}
__device__ __forceinline__ void ldm4(uint32_t addr, uint32_t r[4]) {
    asm volatile("ldmatrix.sync.aligned.m8n8.x4.shared.b16 {%0,%1,%2,%3}, [%4];"
                 : "=r"(r[0]), "=r"(r[1]), "=r"(r[2]), "=r"(r[3]) : "r"(addr));
}
__device__ __forceinline__ void mma16816(float c[4], const uint32_t a[4],
                                         uint32_t b0, uint32_t b1) {
    asm volatile("mma.sync.aligned.m16n8k16.row.col.f32.bf16.bf16.f32 "
                 "{%0,%1,%2,%3}, {%4,%5,%6,%7}, {%8,%9}, {%0,%1,%2,%3};"
                 : "+f"(c[0]), "+f"(c[1]), "+f"(c[2]), "+f"(c[3])
                 : "r"(a[0]), "r"(a[1]), "r"(a[2]), "r"(a[3]), "r"(b0), "r"(b1));
}

// ---------------- replay-safe grid barrier ----------------
// Barrier j uses g_bars[j]; passers reset g_bars[j-2] (all CTAs provably passed it).
// Counters 5,6 are reset in the kernel prologue (before any barrier use).
__device__ __forceinline__ void grid_barrier(int j) {
    __syncthreads();
    if (threadIdx.x == 0) {
        unsigned* ctr = &g_bars[j];
        asm volatile("red.release.gpu.add.u32 [%0], 1;" :: "l"(ctr) : "memory");
        unsigned v;
        do {
            asm volatile("ld.acquire.gpu.u32 %0, [%1];" : "=r"(v) : "l"(ctr) : "memory");
        } while (v < (unsigned)GRIDSZ);
        if (j >= 2)
            asm volatile("st.relaxed.gpu.u32 [%0], 0;" :: "l"(&g_bars[j - 2]) : "memory");
    }
    __syncthreads();
}

// ---------------- weight conversion: fp32 [K][N] -> bf16 hi/lo [N][K] swizzled ----------------
// One thread handles 8 consecutive k for one n == exactly one 16B swizzled chunk:
// conflict-free STS.128 for hi and lo; source reads coalesced (lane-consecutive n).
__device__ void conv_w8(uint8_t* smem, const float* __restrict__ W, int K, int N,
                        uint32_t offH, uint32_t offL, int tid)
{
    const uint32_t stride = (uint32_t)K * 2u;
    const int total = (K >> 3) * N;
    for (int idx = tid; idx < total; idx += NT) {
        const int kg = idx / N, n = idx % N;
        float f[8];
#pragma unroll
        for (int j = 0; j < 8; j++) f[j] = W[(kg * 8 + j) * N + n];
        uint32_t hp[4], lp[4];
#pragma unroll
        for (int p = 0; p < 4; p++) split2(f[2 * p], f[2 * p + 1], hp[p], lp[p]);
        const uint32_t byte = (uint32_t)n * stride + (uint32_t)((kg ^ (n & 7)) << 4);
        *(uint4*)(smem + offH + byte) = make_uint4(hp[0], hp[1], hp[2], hp[3]);
        *(uint4*)(smem + offL + byte) = make_uint4(lp[0], lp[1], lp[2], lp[3]);
    }
}

// ---------------- warp-tile GEMM (XOR-swizzled A and W) ----------------
template <int KSTEPS, int NB8>
__device__ __forceinline__ void mma_swz(uint32_t aHi, uint32_t aLo, uint32_t strideA,
                                        uint32_t wHi, uint32_t wLo, uint32_t strideW,
                                        int mt, int n0, int lane, float acc[][4])
{
#pragma unroll
    for (int i = 0; i < NB8; i++) { acc[i][0] = acc[i][1] = acc[i][2] = acc[i][3] = 0.f; }
    const int arow = mt * 16 + (lane & 15);
    const uint32_t abase = (uint32_t)arow * strideA;
    const uint32_t asel = (uint32_t)(lane >> 4);
    const int brow = lane & 15;
    const uint32_t bsel = (uint32_t)(lane >> 4);
#pragma unroll
    for (int kb = 0; kb < KSTEPS; kb++) {
        const uint32_t au = ((((uint32_t)kb * 2u + asel) ^ (uint32_t)(arow & 7)) << 4);
        uint32_t ah[4], al[4];
        ldm4(aHi + abase + au, ah);
        ldm4(aLo + abase + au, al);
#pragma unroll
        for (int s = 0; s < NB8 / 2; s++) {
            const int n = n0 + s * 16 + brow;
            const uint32_t c = ((uint32_t)kb << 1) | bsel;
            const uint32_t boff = (uint32_t)n * strideW + ((c ^ (uint32_t)(n & 7)) << 4);
            uint32_t bh[4], bl[4];
            ldm4(wHi + boff, bh);
            ldm4(wLo + boff, bl);
            mma16816(acc[s * 2 + 0], ah, bh[0], bh[2]);
            mma16816(acc[s * 2 + 0], ah, bl[0], bl[2]);
            mma16816(acc[s * 2 + 0], al, bh[0], bh[2]);
            mma16816(acc[s * 2 + 1], ah, bh[1], bh[3]);
            mma16816(acc[s * 2 + 1], ah, bl[1], bl[3]);
            mma16816(acc[s * 2 + 1], al, bh[1], bh[3]);
        }
    }
}

// ---------------- epilogues ----------------
template <int NB8>
__device__ __forceinline__ void epi_mid(const float acc[][4], const float* bias,
                                        uint8_t* smem, uint32_t outHi, uint32_t outLo,
                                        uint32_t strideOut, int mt, int n0, int lane)
{
    const int qr = lane >> 2, qc = (lane & 3) * 2;
#pragma unroll
    for (int nf = 0; nf < NB8; nf++) {
        const int col = n0 + nf * 8 + qc;
        const float b0 = bias[col], b1 = bias[col + 1];
#pragma unroll
        for (int hf = 0; hf < 2; hf++) {
            const int row = mt * 16 + qr + hf * 8;
            float f0 = leaky(acc[nf][hf * 2 + 0] + b0);
            float f1 = leaky(acc[nf][hf * 2 + 1] + b1);
            uint32_t hi, lo; split2(f0, f1, hi, lo);
            const uint32_t byte = (uint32_t)row * strideOut +
                ((((uint32_t)(col >> 3)) ^ (uint32_t)(row & 7)) << 4) + (uint32_t)(col & 7) * 2u;
            *(uint32_t*)(smem + outHi + byte) = hi;
            *(uint32_t*)(smem + outLo + byte) = lo;
        }
    }
}

__device__ __forceinline__ void epi_final(const float acc[][4], const float* bias,
                                          float* __restrict__ gout, int mt, int n0, int lane)
{
    const int qr = lane >> 2, qc = (lane & 3) * 2;
#pragma unroll
    for (int nf = 0; nf < 4; nf++) {
        const int col = n0 + nf * 8 + qc;
        const float b0 = bias[col], b1 = bias[col + 1];
#pragma unroll
        for (int hf = 0; hf < 2; hf++) {
            const int row = mt * 16 + qr + hf * 8;
            *(float2*)&gout[(size_t)row * DIM + col] =
                make_float2(acc[nf][hf * 2 + 0] + b0, acc[nf][hf * 2 + 1] + b1);
        }
    }
}

// ---------------- fills ----------------
__device__ __forceinline__ void store_row_swz(uint8_t* smem, int row, int lane, float4 v)
{
    uint32_t h0, l0, h1, l1;
    split2(v.x, v.y, h0, l0);
    split2(v.z, v.w, h1, l1);
    const uint32_t byte = (uint32_t)row * 256u +
        ((((uint32_t)(lane >> 1)) ^ (uint32_t)(row & 7)) << 4) + (uint32_t)(lane & 1) * 8u;
    *(uint2*)(smem + OFF_AH + byte) = make_uint2(h0, h1);
    *(uint2*)(smem + OFF_AL + byte) = make_uint2(l0, l1);
}

// phase0 fill: loads hin rows, ALSO copies them to h (replaces the host memcpy node)
__device__ __forceinline__ void fill_contig_copy(uint8_t* smem, const float* __restrict__ in,
                                                 float* __restrict__ hout, int nodebase, int tid)
{
    const float4* in4 = (const float4*)(in + (size_t)nodebase * DIM);
    float4* out4 = (float4*)(hout + (size_t)nodebase * DIM);
#pragma unroll
    for (int j = 0; j < 4; j++) {
        const int i = tid + j * NT;
        const int row = i >> 5, c4 = i & 31;
        float4 x = in4[(size_t)row * 32 + c4];
        out4[(size_t)row * 32 + c4] = x;
        uint32_t h0, l0, h1, l1;
        split2(x.x, x.y, h0, l0);
        split2(x.z, x.w, h1, l1);
        const uint32_t byte = (uint32_t)row * 256u +
            ((((uint32_t)(c4 >> 1)) ^ (uint32_t)(row & 7)) << 4) + (uint32_t)(c4 & 1) * 8u;
        *(uint2*)(smem + OFF_AH + byte) = make_uint2(h0, h1);
        *(uint2*)(smem + OFF_AL + byte) = make_uint2(l0, l1);
    }
}

__device__ __forceinline__ void stage_idx(uint8_t* smem, const int* __restrict__ src,
                                          const int* __restrict__ msk, int nodebase, int tid)
{
    if (tid < 256)
        ((int4*)(smem + OFF_IDX))[tid] = ((const int4*)(src + (size_t)nodebase * DEG))[tid];
    else
        ((int4*)(smem + OFF_IDX + 4096))[tid - 256] =
            ((const int4*)(msk + (size_t)nodebase * DEG))[tid - 256];
}

__device__ __forceinline__ void gather_rows(uint8_t* smem,
                                            const float* __restrict__ h,
                                            int w, int lane)
{
    const int* sidx = (const int*)(smem + OFF_IDX);
    const int* midx = sidx + 1024;
    const float* ginv = g_inv;
#pragma unroll
    for (int rr = 0; rr < 4; rr += 2) {
        const int r0 = w * 4 + rr, r1 = r0 + 1;
        float4 a0 = make_float4(0.f, 0.f, 0.f, 0.f);
        float4 a1 = make_float4(0.f, 0.f, 0.f, 0.f);
#pragma unroll 8
        for (int e = 0; e < DEG; e++) {
            const int s0 = sidx[r0 * DEG + e], m0 = midx[r0 * DEG + e];
            const int s1 = sidx[r1 * DEG + e], m1 = midx[r1 * DEG + e];
            const float4* p0 = (const float4*)((m0 ? ginv : h) + (size_t)s0 * DIM);
            const float4* p1 = (const float4*)((m1 ? ginv : h) + (size_t)s1 * DIM);
            float4 v0 = p0[lane], v1 = p1[lane];
            a0.x += v0.x; a0.y += v0.y; a0.z += v0.z; a0.w += v0.w;
            a1.x += v1.x; a1.y += v1.y; a1.z += v1.z; a1.w += v1.w;
        }
        const float s16 = 0.0625f;
        a0.x *= s16; a0.y *= s16; a0.z *= s16; a0.w *= s16;
        a1.x *= s16; a1.y *= s16; a1.z *= s16; a1.w *= s16;
        store_row_swz(smem, r0, lane, a0);
        store_row_swz(smem, r1, lane, a1);
    }
}

// ---------------- phase 0: std inv-MLP over hin (+copy to h) ----------------
__device__ void phase0(uint8_t* smem, uint32_t SB, const float* __restrict__ hin,
                       float* __restrict__ h, int lane, int w, int tid)
{
    float* BIAS = (float*)(smem + OFF_BIAS);
    const int mt = w & 3, nh = w >> 2;
    const int t0 = blockIdx.x;
    if (t0 < NTILES) fill_contig_copy(smem, hin, h, t0 * 64, tid);
    for (int t = t0; t < NTILES; t += GRIDSZ) {
        __syncthreads();
        const int hn = (t + GRIDSZ) < NTILES;
        float acc[4][4];
        mma_swz<8, 2>(SB + OFF_AH, SB + OFF_AL, 256, SB + SW1H, SB + SW1L, 256,
                      mt, nh * 16, lane, acc);
        epi_mid<2>(acc, BIAS + 512, smem, OFF_BH, OFF_BL, 128, mt, nh * 16, lane);
        __syncthreads();
        if (hn) fill_contig_copy(smem, hin, h, (t + GRIDSZ) * 64, tid);
        mma_swz<4, 2>(SB + OFF_BH, SB + OFF_BL, 128, SB + SW2IH, SB + SW2IL, 128,
                      mt, nh * 16, lane, acc);
        epi_mid<2>(acc, BIAS + 320, smem, OFF_CH, OFF_CL, 128, mt, nh * 16, lane);
        __syncthreads();
        mma_swz<4, 4>(SB + OFF_CH, SB + OFF_CL, 128, SB + SW3IH, SB + SW3IL, 128,
                      mt, nh * 32, lane, acc);
        epi_final(acc, BIAS + 384, g_inv + (size_t)t * 64 * DIM, mt, nh * 32, lane);
    }
}

// ---------------- level phase: gather -> and-MLP -> (fused inv-MLP) ----------------
__device__ void phase_level(uint8_t* smem, uint32_t SB, float* __restrict__ h,
                            const int* __restrict__ src, const int* __restrict__ msk,
                            int lvl, int do_inv, int lane, int w, int tid)
{
    float* BIAS = (float*)(smem + OFF_BIAS);
    const int mt = w & 3, nh = w >> 2;
    float* hout = h + (size_t)(lvl + 1) * NPL * DIM;
    float* gout = g_inv + (size_t)(lvl + 1) * NPL * DIM;
    const int t0 = blockIdx.x;
    if (t0 < NTILES) {
        stage_idx(smem, src, msk, t0 * 64, tid);
        __syncthreads();
        gather_rows(smem, h, w, lane);
    }
    for (int t = t0; t < NTILES; t += GRIDSZ) {
        __syncthreads();                       // A + idx consistent
        const int hn = (t + GRIDSZ) < NTILES;
        float acc[4][4];
        // S1: and-L1
        mma_swz<8, 2>(SB + OFF_AH, SB + OFF_AL, 256, SB + SW1H, SB + SW1L, 256,
                      mt, nh * 16, lane, acc);
        epi_mid<2>(acc, BIAS, smem, OFF_BH, OFF_BL, 128, mt, nh * 16, lane);
        if (hn) stage_idx(smem, src, msk, (t + GRIDSZ) * 64, tid);
        __syncthreads();                       // B ready, A free, idx visible
        // overlap: gather next tile into A while L2/L3 run
        if (hn) gather_rows(smem, h, w, lane);
        // S2: and-L2
        mma_swz<4, 2>(SB + OFF_BH, SB + OFF_BL, 128, SB + SW2AH, SB + SW2AL, 128,
                      mt, nh * 16, lane, acc);
        epi_mid<2>(acc, BIAS + 64, smem, OFF_CH, OFF_CL, 128, mt, nh * 16, lane);
        __syncthreads();                       // C ready, B free
        // S3: and-L3 -> h  |  fused inv-L1 (K=64, reads C) -> B
        mma_swz<4, 4>(SB + OFF_CH, SB + OFF_CL, 128, SB + SW3AH, SB + SW3AL, 128,
                      mt, nh * 32, lane, acc);
        epi_final(acc, BIAS + 128, hout + (size_t)t * 64 * DIM, mt, nh * 32, lane);
        if (do_inv) {
            mma_swz<4, 2>(SB + OFF_CH, SB + OFF_CL, 128, SB + SWFH, SB + SWFL, 128,
                          mt, nh * 16, lane, acc);
            epi_mid<2>(acc, BIAS + 256, smem, OFF_BH, OFF_BL, 128, mt, nh * 16, lane);
            __syncthreads();                   // B ready, C free
            // S4: inv-L2
            mma_swz<4, 2>(SB + OFF_BH, SB + OFF_BL, 128, SB + SW2IH, SB + SW2IL, 128,
                          mt, nh * 16, lane, acc);
            epi_mid<2>(acc, BIAS + 320, smem, OFF_CH, OFF_CL, 128, mt, nh * 16, lane);
            __syncthreads();                   // C ready
            // S5: inv-L3 -> g_inv
            mma_swz<4, 4>(SB + OFF_CH, SB + OFF_CL, 128, SB + SW3IH, SB + SW3IL, 128,
                          mt, nh * 32, lane, acc);
            epi_final(acc, BIAS + 384, gout + (size_t)t * 64 * DIM, mt, nh * 32, lane);
        }
    }
}

// ---------------- persistent kernel (single launch, everything inside) ----------------
__global__ __launch_bounds__(NT, 1)
void persist_kernel(const float* __restrict__ hin, float* __restrict__ h,
                    const int* __restrict__ esrc, const int* __restrict__ emask,
                    const float* aw1, const float* ab1, const float* aw2, const float* ab2,
                    const float* aw3, const float* ab3,
                    const float* iw1, const float* ib1, const float* iw2, const float* ib2,
                    const float* iw3, const float* ib3)
{
    extern __shared__ __align__(16) uint8_t smem[];
    const uint32_t SB = smem_u32(smem);
    const int tid = threadIdx.x, lane = tid & 31, w = tid >> 5;
    float* BIAS = (float*)(smem + OFF_BIAS);

    // --- prologue: reset replay-stale barrier counters (before any barrier use) ---
    if (tid == 0) {
        asm volatile("st.relaxed.gpu.u32 [%0], 0;" :: "l"(&g_bars[5]) : "memory");
        asm volatile("st.relaxed.gpu.u32 [%0], 0;" :: "l"(&g_bars[6]) : "memory");
    }

    // --- stage iw1 fp32 (32KB -> A region) and aw3 fp32 (32KB -> B/C region) ---
    {
        float4* d0 = (float4*)(smem + OFF_AH);
        const float4* s0 = (const float4*)iw1;
        for (int i = tid; i < 2048; i += NT) d0[i] = s0[i];
        float4* d1 = (float4*)(smem + OFF_BH);
        const float4* s1 = (const float4*)aw3;
        for (int i = tid; i < 2048; i += NT) d1[i] = s1[i];
    }
    __syncthreads();

    // --- fused WF = W3a @ W1i (operands in smem; register-tiled, broadcast-friendly) ---
    {
        const float* s_iw1 = (const float*)(smem + OFF_AH);   // [128][64]
        const float* s_aw3 = (const float*)(smem + OFF_BH);   // [64][128]
        const int n = tid & 63;
        const int c0 = (tid >> 6) * 8;
        float acc[8];
#pragma unroll
        for (int i = 0; i < 8; i++) acc[i] = 0.f;
        for (int kc = 0; kc < 128; kc += 16) {
            float iv[16];
#pragma unroll
            for (int j = 0; j < 16; j++) iv[j] = s_iw1[(kc + j) * 64 + n];
#pragma unroll
            for (int ci = 0; ci < 8; ci++) {
                const float* row = s_aw3 + (c0 + ci) * 128 + kc;
#pragma unroll
                for (int j = 0; j < 16; j += 4) {
                    float4 a = *(const float4*)(row + j);
                    acc[ci] += a.x * iv[j] + a.y * iv[j + 1] + a.z * iv[j + 2] + a.w * iv[j + 3];
                }
            }
        }
#pragma unroll
        for (int ci = 0; ci < 8; ci++) {
            const int c = c0 + ci;
            __nv_bfloat16 hv = __float2bfloat16(acc[ci]);
            __nv_bfloat16 lv = __float2bfloat16(acc[ci] - __bfloat162float(hv));
            const uint32_t byte = (uint32_t)n * 128u +
                ((((uint32_t)(c >> 3) ^ (uint32_t)(n & 7)) << 4)) + (uint32_t)(c & 7) * 2u;
            *(__nv_bfloat16*)(smem + SWFH + byte) = hv;
            *(__nv_bfloat16*)(smem + SWFL + byte) = lv;
        }
        // fused bias -> BIAS[256..319]
        if (tid < 64) {
            float s0 = 0.f, s1 = 0.f, s2 = 0.f, s3 = 0.f;
#pragma unroll 8
            for (int k = 0; k < 128; k += 4) {
                s0 += __ldg(&ab3[k + 0]) * s_iw1[(k + 0) * 64 + tid];
                s1 += __ldg(&ab3[k + 1]) * s_iw1[(k + 1) * 64 + tid];
                s2 += __ldg(&ab3[k + 2]) * s_iw1[(k + 2) * 64 + tid];
                s3 += __ldg(&ab3[k + 3]) * s_iw1[(k + 3) * 64 + tid];
            }
            BIAS[256 + tid] = (s0 + s1) + (s2 + s3) + ib1[tid];
        }
        // conversions: conflict-free 16B chunk per thread. iw1/aw3 from smem scratch.
        conv_w8(smem, s_iw1, 128, 64,  SW1H,  SW1L,  tid);   // slot0 <- W1i (phase0)
        conv_w8(smem, s_aw3, 64,  128, SW3AH, SW3AL, tid);
        conv_w8(smem, aw2,   64,  64,  SW2AH, SW2AL, tid);
        conv_w8(smem, iw2,   64,  64,  SW2IH, SW2IL, tid);
        conv_w8(smem, iw3,   64,  128, SW3IH, SW3IL, tid);
    }
    if (tid < 64) {
        BIAS[tid] = ab1[tid];       BIAS[64 + tid] = ab2[tid];
        BIAS[320 + tid] = ib2[tid]; BIAS[512 + tid] = ib1[tid];
    }
    if (tid < 128) { BIAS[128 + tid] = ab3[tid]; BIAS[384 + tid] = ib3[tid]; }
    __syncthreads();

    phase0(smem, SB, hin, h, lane, w, tid);

    // reconvert slot0 <- W1a for level phases
    __syncthreads();
    conv_w8(smem, aw1, 128, 64, SW1H, SW1L, tid);
    grid_barrier(0);

    for (int lvl = 0; lvl < 7; lvl++) {
        const int* src = esrc  + (size_t)lvl * NPL * DEG;
        const int* msk = emask + (size_t)lvl * NPL * DEG;
        phase_level(smem, SB, h, src, msk, lvl, (lvl < 6) ? 1 : 0, lane, w, tid);
        if (lvl < 6) grid_barrier(1 + lvl);
    }
}

// ---------------------------------------------------------------------------
extern "C" void kernel_launch(void* const* d_in, const int* in_sizes, int n_in,
                              void* d_out, int out_size)
{
    (void)in_sizes; (void)n_in; (void)out_size;
    const float* h_in  = (const float*)d_in[0];
    const int*   esrc  = (const int*)d_in[1];
    const int*   emask = (const int*)d_in[2];
    const float* iw1 = (const float*)d_in[3];
    const float* ib1 = (const float*)d_in[4];
    const float* iw2 = (const float*)d_in[5];
    const float* ib2 = (const float*)d_in[6];
    const float* iw3 = (const float*)d_in[7];
    const float* ib3 = (const float*)d_in[8];
    const float* aw1 = (const float*)d_in[9];
    const float* ab1 = (const float*)d_in[10];
    const float* aw2 = (const float*)d_in[11];
    const float* ab2 = (const float*)d_in[12];
    const float* aw3 = (const float*)d_in[13];
    const float* ab3 = (const float*)d_in[14];

    float* h = (float*)d_out;

    static bool once = false;
    if (!once) {
        cudaFuncSetAttribute(persist_kernel, cudaFuncAttributeMaxDynamicSharedMemorySize, SM_TOTAL);
        once = true;
    }

    // single kernel launch: weight conversion, h level-0 copy, all 8 phases inside
    persist_kernel<<<GRIDSZ, NT, SM_TOTAL>>>(h_in, h, esrc, emask,
                                             aw1, ab1, aw2, ab2, aw3, ab3,
                                             iw1, ib1, iw2, ib2, iw3, ib3);
}

// round 16
// speedup vs baseline: 1.0041x; 1.0041x over previous
#include <cuda_runtime.h>
#include <cuda_bf16.h>
#include <cstdint>

#define NPL    16384
#define DEG    16
#define DIM    128
#define NT     512
#define GRIDSZ 148
#define NTILES 256            // 64-row tiles per level

// ---- weight slots in smem (bytes). [N][K] bf16, XOR-16B swizzle ----
#define SW1H  0               // 32KB slot: W1a (levels) or W1i-std (phase0)
#define SW1L  16384
#define SW2AH 32768
#define SW2AL 40960
#define SW3AH 49152
#define SW3AL 65536
#define SWFH  81920           // fused WF = W3a @ W1i  (64x64)
#define SWFL  90112
#define SW2IH 98304
#define SW2IL 106496
#define SW3IH 114688
#define SW3IL 131072
#define WTOT  147456

// ---- smem layout (bytes) ----
#define OFF_AH   147456       // A [64][256B] hi   (prologue: iw1 fp32 scratch, 32KB)
#define OFF_AL   163840
#define OFF_BH   180224       // B [64][128B] hi   (prologue: aw3 fp32 scratch, 32KB)
#define OFF_BL   188416
#define OFF_CH   196608       // C [64][128B] hi
#define OFF_CL   204800
#define OFF_IDX  212992       // src 4KB + mask 4KB
#define OFF_BIAS 221184       // 576 floats
#define SM_TOTAL 223744

__device__ __align__(16) float g_inv[7 * NPL * DIM];
__device__ unsigned g_bars[8];          // zero-initialized at module load

__device__ __forceinline__ float leaky(float v) { return v >= 0.f ? v : 0.01f * v; }

__device__ __forceinline__ void split2(float f0, float f1, uint32_t& hi, uint32_t& lo) {
    asm("cvt.rn.bf16x2.f32 %0, %1, %2;" : "=r"(hi) : "f"(f1), "f"(f0));
    float hf0 = __uint_as_float(hi << 16);
    float hf1 = __uint_as_float(hi & 0xFFFF0000u);
    float r0 = f0 - hf0, r1 = f1 - hf1;
    asm("cvt.rn.bf16x2.f32 %0, %1, %2;" : "=r"(lo) : "f"(r1), "f"(r0));
}

__device__ __forceinline__ uint32_t smem_u32(const void* p) {
    uint32_t a;
    asm("{ .reg .u64 t; cvta.to.shared.u64 t, %1; cvt.u32.u64 %0, t; }" : "=r"(a) : "l"(p));
    return a;
}
__device__ __forceinline__ void ldm4(uint32_t addr, uint32_t r[4]) {
    asm volatile("ldmatrix.sync.aligned.m8n8.x4.shared.b16 {%0,%1,%2,%3}, [%4];"
                 : "=r"(r[0]), "=r"(r[1]), "=r"(r[2]), "=r"(r[3]) : "r"(addr));
}
__device__ __forceinline__ void mma16816(float c[4], const uint32_t a[4],
                                         uint32_t b0, uint32_t b1) {
    asm volatile("mma.sync.aligned.m16n8k16.row.col.f32.bf16.bf16.f32 "
                 "{%0,%1,%2,%3}, {%4,%5,%6,%7}, {%8,%9}, {%0,%1,%2,%3};"
                 : "+f"(c[0]), "+f"(c[1]), "+f"(c[2]), "+f"(c[3])
                 : "r"(a[0]), "r"(a[1]), "r"(a[2]), "r"(a[3]), "r"(b0), "r"(b1));
}

// ---------------- replay-safe grid barrier ----------------
// Barrier j uses g_bars[j]; passers reset g_bars[j-2] (all CTAs provably passed it).
// Counters 5,6 are reset in the kernel prologue (before any barrier use).
__device__ __forceinline__ void grid_barrier(int j) {
    __syncthreads();
    if (threadIdx.x == 0) {
        unsigned* ctr = &g_bars[j];
        asm volatile("red.release.gpu.add.u32 [%0], 1;" :: "l"(ctr) : "memory");
        unsigned v;
        do {
            asm volatile("ld.acquire.gpu.u32 %0, [%1];" : "=r"(v) : "l"(ctr) : "memory");
        } while (v < (unsigned)GRIDSZ);
        if (j >= 2)
            asm volatile("st.relaxed.gpu.u32 [%0], 0;" :: "l"(&g_bars[j - 2]) : "memory");
    }
    __syncthreads();
}

// ---------------- weight conversion: fp32 [K][N] -> bf16 hi/lo [N][K] swizzled ----------------
// One thread handles 8 consecutive k for one n == exactly one 16B swizzled chunk:
// conflict-free STS.128 for hi and lo; source reads coalesced (lane-consecutive n).
__device__ void conv_w8(uint8_t* smem, const float* __restrict__ W, int K, int N,
                        uint32_t offH, uint32_t offL, int tid)
{
    const uint32_t stride = (uint32_t)K * 2u;
    const int total = (K >> 3) * N;
    for (int idx = tid; idx < total; idx += NT) {
        const int kg = idx / N, n = idx % N;
        float f[8];
#pragma unroll
        for (int j = 0; j < 8; j++) f[j] = W[(kg * 8 + j) * N + n];
        uint32_t hp[4], lp[4];
#pragma unroll
        for (int p = 0; p < 4; p++) split2(f[2 * p], f[2 * p + 1], hp[p], lp[p]);
        const uint32_t byte = (uint32_t)n * stride + (uint32_t)((kg ^ (n & 7)) << 4);
        *(uint4*)(smem + offH + byte) = make_uint4(hp[0], hp[1], hp[2], hp[3]);
        *(uint4*)(smem + offL + byte) = make_uint4(lp[0], lp[1], lp[2], lp[3]);
    }
}

// ---------------- warp-tile GEMM (XOR-swizzled A and W) ----------------
template <int KSTEPS, int NB8>
__device__ __forceinline__ void mma_swz(uint32_t aHi, uint32_t aLo, uint32_t strideA,
                                        uint32_t wHi, uint32_t wLo, uint32_t strideW,
                                        int mt, int n0, int lane, float acc[][4])
{
#pragma unroll
    for (int i = 0; i < NB8; i++) { acc[i][0] = acc[i][1] = acc[i][2] = acc[i][3] = 0.f; }
    const int arow = mt * 16 + (lane & 15);
    const uint32_t abase = (uint32_t)arow * strideA;
    const uint32_t asel = (uint32_t)(lane >> 4);
    const int brow = lane & 15;
    const uint32_t bsel = (uint32_t)(lane >> 4);
#pragma unroll
    for (int kb = 0; kb < KSTEPS; kb++) {
        const uint32_t au = ((((uint32_t)kb * 2u + asel) ^ (uint32_t)(arow & 7)) << 4);
        uint32_t ah[4], al[4];
        ldm4(aHi + abase + au, ah);
        ldm4(aLo + abase + au, al);
#pragma unroll
        for (int s = 0; s < NB8 / 2; s++) {
            const int n = n0 + s * 16 + brow;
            const uint32_t c = ((uint32_t)kb << 1) | bsel;
            const uint32_t boff = (uint32_t)n * strideW + ((c ^ (uint32_t)(n & 7)) << 4);
            uint32_t bh[4], bl[4];
            ldm4(wHi + boff, bh);
            ldm4(wLo + boff, bl);
            mma16816(acc[s * 2 + 0], ah, bh[0], bh[2]);
            mma16816(acc[s * 2 + 0], ah, bl[0], bl[2]);
            mma16816(acc[s * 2 + 0], al, bh[0], bh[2]);
            mma16816(acc[s * 2 + 1], ah, bh[1], bh[3]);
            mma16816(acc[s * 2 + 1], ah, bl[1], bl[3]);
            mma16816(acc[s * 2 + 1], al, bh[1], bh[3]);
        }
    }
}

// ---------------- epilogues ----------------
template <int NB8>
__device__ __forceinline__ void epi_mid(const float acc[][4], const float* bias,
                                        uint8_t* smem, uint32_t outHi, uint32_t outLo,
                                        uint32_t strideOut, int mt, int n0, int lane)
{
    const int qr = lane >> 2, qc = (lane & 3) * 2;
#pragma unroll
    for (int nf = 0; nf < NB8; nf++) {
        const int col = n0 + nf * 8 + qc;
        const float b0 = bias[col], b1 = bias[col + 1];
#pragma unroll
        for (int hf = 0; hf < 2; hf++) {
            const int row = mt * 16 + qr + hf * 8;
            float f0 = leaky(acc[nf][hf * 2 + 0] + b0);
            float f1 = leaky(acc[nf][hf * 2 + 1] + b1);
            uint32_t hi, lo; split2(f0, f1, hi, lo);
            const uint32_t byte = (uint32_t)row * strideOut +
                ((((uint32_t)(col >> 3)) ^ (uint32_t)(row & 7)) << 4) + (uint32_t)(col & 7) * 2u;
            *(uint32_t*)(smem + outHi + byte) = hi;
            *(uint32_t*)(smem + outLo + byte) = lo;
        }
    }
}

__device__ __forceinline__ void epi_final(const float acc[][4], const float* bias,
                                          float* __restrict__ gout, int mt, int n0, int lane)
{
    const int qr = lane >> 2, qc = (lane & 3) * 2;
#pragma unroll
    for (int nf = 0; nf < 4; nf++) {
        const int col = n0 + nf * 8 + qc;
        const float b0 = bias[col], b1 = bias[col + 1];
#pragma unroll
        for (int hf = 0; hf < 2; hf++) {
            const int row = mt * 16 + qr + hf * 8;
            *(float2*)&gout[(size_t)row * DIM + col] =
                make_float2(acc[nf][hf * 2 + 0] + b0, acc[nf][hf * 2 + 1] + b1);
        }
    }
}

// ---------------- fills ----------------
__device__ __forceinline__ void store_row_swz(uint8_t* smem, int row, int lane, float4 v)
{
    uint32_t h0, l0, h1, l1;
    split2(v.x, v.y, h0, l0);
    split2(v.z, v.w, h1, l1);
    const uint32_t byte = (uint32_t)row * 256u +
        ((((uint32_t)(lane >> 1)) ^ (uint32_t)(row & 7)) << 4) + (uint32_t)(lane & 1) * 8u;
    *(uint2*)(smem + OFF_AH + byte) = make_uint2(h0, h1);
    *(uint2*)(smem + OFF_AL + byte) = make_uint2(l0, l1);
}

// phase0 fill: loads hin rows, ALSO copies them to h (replaces the host memcpy node)
__device__ __forceinline__ void fill_contig_copy(uint8_t* smem, const float* __restrict__ in,
                                                 float* __restrict__ hout, int nodebase, int tid)
{
    const float4* in4 = (const float4*)(in + (size_t)nodebase * DIM);
    float4* out4 = (float4*)(hout + (size_t)nodebase * DIM);
#pragma unroll
    for (int j = 0; j < 4; j++) {
        const int i = tid + j * NT;
        const int row = i >> 5, c4 = i & 31;
        float4 x = in4[(size_t)row * 32 + c4];
        out4[(size_t)row * 32 + c4] = x;
        uint32_t h0, l0, h1, l1;
        split2(x.x, x.y, h0, l0);
        split2(x.z, x.w, h1, l1);
        const uint32_t byte = (uint32_t)row * 256u +
            ((((uint32_t)(c4 >> 1)) ^ (uint32_t)(row & 7)) << 4) + (uint32_t)(c4 & 1) * 8u;
        *(uint2*)(smem + OFF_AH + byte) = make_uint2(h0, h1);
        *(uint2*)(smem + OFF_AL + byte) = make_uint2(l0, l1);
    }
}

__device__ __forceinline__ void stage_idx(uint8_t* smem, const int* __restrict__ src,
                                          const int* __restrict__ msk, int nodebase, int tid)
{
    if (tid < 256)
        ((int4*)(smem + OFF_IDX))[tid] = ((const int4*)(src + (size_t)nodebase * DEG))[tid];
    else
        ((int4*)(smem + OFF_IDX + 4096))[tid - 256] =
            ((const int4*)(msk + (size_t)nodebase * DEG))[tid - 256];
}

__device__ __forceinline__ void gather_rows(uint8_t* smem,
                                            const float* __restrict__ h,
                                            int w, int lane)
{
    const int* sidx = (const int*)(smem + OFF_IDX);
    const int* midx = sidx + 1024;
    const float* ginv = g_inv;
#pragma unroll
    for (int rr = 0; rr < 4; rr += 2) {
        const int r0 = w * 4 + rr, r1 = r0 + 1;
        float4 a0 = make_float4(0.f, 0.f, 0.f, 0.f);
        float4 a1 = make_float4(0.f, 0.f, 0.f, 0.f);
#pragma unroll 8
        for (int e = 0; e < DEG; e++) {
            const int s0 = sidx[r0 * DEG + e], m0 = midx[r0 * DEG + e];
            const int s1 = sidx[r1 * DEG + e], m1 = midx[r1 * DEG + e];
            const float4* p0 = (const float4*)((m0 ? ginv : h) + (size_t)s0 * DIM);
            const float4* p1 = (const float4*)((m1 ? ginv : h) + (size_t)s1 * DIM);
            float4 v0 = p0[lane], v1 = p1[lane];
            a0.x += v0.x; a0.y += v0.y; a0.z += v0.z; a0.w += v0.w;
            a1.x += v1.x; a1.y += v1.y; a1.z += v1.z; a1.w += v1.w;
        }
        const float s16 = 0.0625f;
        a0.x *= s16; a0.y *= s16; a0.z *= s16; a0.w *= s16;
        a1.x *= s16; a1.y *= s16; a1.z *= s16; a1.w *= s16;
        store_row_swz(smem, r0, lane, a0);
        store_row_swz(smem, r1, lane, a1);
    }
}

// ---------------- phase 0: std inv-MLP over hin (+copy to h) ----------------
__device__ void phase0(uint8_t* smem, uint32_t SB, const float* __restrict__ hin,
                       float* __restrict__ h, int lane, int w, int tid)
{
    float* BIAS = (float*)(smem + OFF_BIAS);
    const int mt = w & 3, nh = w >> 2;
    const int t0 = blockIdx.x;
    if (t0 < NTILES) fill_contig_copy(smem, hin, h, t0 * 64, tid);
    for (int t = t0; t < NTILES; t += GRIDSZ) {
        __syncthreads();
        const int hn = (t + GRIDSZ) < NTILES;
        float acc[4][4];
        mma_swz<8, 2>(SB + OFF_AH, SB + OFF_AL, 256, SB + SW1H, SB + SW1L, 256,
                      mt, nh * 16, lane, acc);
        epi_mid<2>(acc, BIAS + 512, smem, OFF_BH, OFF_BL, 128, mt, nh * 16, lane);
        __syncthreads();
        if (hn) fill_contig_copy(smem, hin, h, (t + GRIDSZ) * 64, tid);
        mma_swz<4, 2>(SB + OFF_BH, SB + OFF_BL, 128, SB + SW2IH, SB + SW2IL, 128,
                      mt, nh * 16, lane, acc);
        epi_mid<2>(acc, BIAS + 320, smem, OFF_CH, OFF_CL, 128, mt, nh * 16, lane);
        __syncthreads();
        mma_swz<4, 4>(SB + OFF_CH, SB + OFF_CL, 128, SB + SW3IH, SB + SW3IL, 128,
                      mt, nh * 32, lane, acc);
        epi_final(acc, BIAS + 384, g_inv + (size_t)t * 64 * DIM, mt, nh * 32, lane);
    }
}

// ---------------- level phase: gather -> and-MLP -> (fused inv-MLP) ----------------
__device__ void phase_level(uint8_t* smem, uint32_t SB, float* __restrict__ h,
                            const int* __restrict__ src, const int* __restrict__ msk,
                            int lvl, int do_inv, int lane, int w, int tid)
{
    float* BIAS = (float*)(smem + OFF_BIAS);
    const int mt = w & 3, nh = w >> 2;
    float* hout = h + (size_t)(lvl + 1) * NPL * DIM;
    float* gout = g_inv + (size_t)(lvl + 1) * NPL * DIM;
    const int t0 = blockIdx.x;
    if (t0 < NTILES) {
        stage_idx(smem, src, msk, t0 * 64, tid);
        __syncthreads();
        gather_rows(smem, h, w, lane);
    }
    for (int t = t0; t < NTILES; t += GRIDSZ) {
        __syncthreads();                       // A + idx consistent
        const int hn = (t + GRIDSZ) < NTILES;
        float acc[4][4];
        // S1: and-L1
        mma_swz<8, 2>(SB + OFF_AH, SB + OFF_AL, 256, SB + SW1H, SB + SW1L, 256,
                      mt, nh * 16, lane, acc);
        epi_mid<2>(acc, BIAS, smem, OFF_BH, OFF_BL, 128, mt, nh * 16, lane);
        if (hn) stage_idx(smem, src, msk, (t + GRIDSZ) * 64, tid);
        __syncthreads();                       // B ready, A free, idx visible
        // overlap: gather next tile into A while L2/L3 run
        if (hn) gather_rows(smem, h, w, lane);
        // S2: and-L2
        mma_swz<4, 2>(SB + OFF_BH, SB + OFF_BL, 128, SB + SW2AH, SB + SW2AL, 128,
                      mt, nh * 16, lane, acc);
        epi_mid<2>(acc, BIAS + 64, smem, OFF_CH, OFF_CL, 128, mt, nh * 16, lane);
        __syncthreads();                       // C ready, B free
        // S3: and-L3 -> h  |  fused inv-L1 (K=64, reads C) -> B
        mma_swz<4, 4>(SB + OFF_CH, SB + OFF_CL, 128, SB + SW3AH, SB + SW3AL, 128,
                      mt, nh * 32, lane, acc);
        epi_final(acc, BIAS + 128, hout + (size_t)t * 64 * DIM, mt, nh * 32, lane);
        if (do_inv) {
            mma_swz<4, 2>(SB + OFF_CH, SB + OFF_CL, 128, SB + SWFH, SB + SWFL, 128,
                          mt, nh * 16, lane, acc);
            epi_mid<2>(acc, BIAS + 256, smem, OFF_BH, OFF_BL, 128, mt, nh * 16, lane);
            __syncthreads();                   // B ready, C free
            // S4: inv-L2
            mma_swz<4, 2>(SB + OFF_BH, SB + OFF_BL, 128, SB + SW2IH, SB + SW2IL, 128,
                          mt, nh * 16, lane, acc);
            epi_mid<2>(acc, BIAS + 320, smem, OFF_CH, OFF_CL, 128, mt, nh * 16, lane);
            __syncthreads();                   // C ready
            // S5: inv-L3 -> g_inv
            mma_swz<4, 4>(SB + OFF_CH, SB + OFF_CL, 128, SB + SW3IH, SB + SW3IL, 128,
                          mt, nh * 32, lane, acc);
            epi_final(acc, BIAS + 384, gout + (size_t)t * 64 * DIM, mt, nh * 32, lane);
        }
    }
}

// ---------------- persistent kernel (single launch, everything inside) ----------------
__global__ __launch_bounds__(NT, 1)
void persist_kernel(const float* __restrict__ hin, float* __restrict__ h,
                    const int* __restrict__ esrc, const int* __restrict__ emask,
                    const float* aw1, const float* ab1, const float* aw2, const float* ab2,
                    const float* aw3, const float* ab3,
                    const float* iw1, const float* ib1, const float* iw2, const float* ib2,
                    const float* iw3, const float* ib3)
{
    extern __shared__ __align__(16) uint8_t smem[];
    const uint32_t SB = smem_u32(smem);
    const int tid = threadIdx.x, lane = tid & 31, w = tid >> 5;
    float* BIAS = (float*)(smem + OFF_BIAS);

    // --- prologue: reset replay-stale barrier counters (before any barrier use) ---
    if (tid == 0) {
        asm volatile("st.relaxed.gpu.u32 [%0], 0;" :: "l"(&g_bars[5]) : "memory");
        asm volatile("st.relaxed.gpu.u32 [%0], 0;" :: "l"(&g_bars[6]) : "memory");
    }

    // --- stage iw1 fp32 (32KB -> A region) and aw3 fp32 (32KB -> B/C region) ---
    {
        float4* d0 = (float4*)(smem + OFF_AH);
        const float4* s0 = (const float4*)iw1;
        for (int i = tid; i < 2048; i += NT) d0[i] = s0[i];
        float4* d1 = (float4*)(smem + OFF_BH);
        const float4* s1 = (const float4*)aw3;
        for (int i = tid; i < 2048; i += NT) d1[i] = s1[i];
    }
    __syncthreads();

    // --- fused WF = W3a @ W1i (operands in smem; register-tiled, broadcast-friendly) ---
    {
        const float* s_iw1 = (const float*)(smem + OFF_AH);   // [128][64]
        const float* s_aw3 = (const float*)(smem + OFF_BH);   // [64][128]
        const int n = tid & 63;
        const int c0 = (tid >> 6) * 8;
        float acc[8];
#pragma unroll
        for (int i = 0; i < 8; i++) acc[i] = 0.f;
        for (int kc = 0; kc < 128; kc += 16) {
            float iv[16];
#pragma unroll
            for (int j = 0; j < 16; j++) iv[j] = s_iw1[(kc + j) * 64 + n];
#pragma unroll
            for (int ci = 0; ci < 8; ci++) {
                const float* row = s_aw3 + (c0 + ci) * 128 + kc;
#pragma unroll
                for (int j = 0; j < 16; j += 4) {
                    float4 a = *(const float4*)(row + j);
                    acc[ci] += a.x * iv[j] + a.y * iv[j + 1] + a.z * iv[j + 2] + a.w * iv[j + 3];
                }
            }
        }
#pragma unroll
        for (int ci = 0; ci < 8; ci++) {
            const int c = c0 + ci;
            __nv_bfloat16 hv = __float2bfloat16(acc[ci]);
            __nv_bfloat16 lv = __float2bfloat16(acc[ci] - __bfloat162float(hv));
            const uint32_t byte = (uint32_t)n * 128u +
                ((((uint32_t)(c >> 3) ^ (uint32_t)(n & 7)) << 4)) + (uint32_t)(c & 7) * 2u;
            *(__nv_bfloat16*)(smem + SWFH + byte) = hv;
            *(__nv_bfloat16*)(smem + SWFL + byte) = lv;
        }
        // fused bias -> BIAS[256..319]
        if (tid < 64) {
            float s0 = 0.f, s1 = 0.f, s2 = 0.f, s3 = 0.f;
#pragma unroll 8
            for (int k = 0; k < 128; k += 4) {
                s0 += __ldg(&ab3[k + 0]) * s_iw1[(k + 0) * 64 + tid];
                s1 += __ldg(&ab3[k + 1]) * s_iw1[(k + 1) * 64 + tid];
                s2 += __ldg(&ab3[k + 2]) * s_iw1[(k + 2) * 64 + tid];
                s3 += __ldg(&ab3[k + 3]) * s_iw1[(k + 3) * 64 + tid];
            }
            BIAS[256 + tid] = (s0 + s1) + (s2 + s3) + ib1[tid];
        }
        // conversions: conflict-free 16B chunk per thread. iw1/aw3 from smem scratch.
        conv_w8(smem, s_iw1, 128, 64,  SW1H,  SW1L,  tid);   // slot0 <- W1i (phase0)
        conv_w8(smem, s_aw3, 64,  128, SW3AH, SW3AL, tid);
        conv_w8(smem, aw2,   64,  64,  SW2AH, SW2AL, tid);
        conv_w8(smem, iw2,   64,  64,  SW2IH, SW2IL, tid);
        conv_w8(smem, iw3,   64,  128, SW3IH, SW3IL, tid);
    }
    if (tid < 64) {
        BIAS[tid] = ab1[tid];       BIAS[64 + tid] = ab2[tid];
        BIAS[320 + tid] = ib2[tid]; BIAS[512 + tid] = ib1[tid];
    }
    if (tid < 128) { BIAS[128 + tid] = ab3[tid]; BIAS[384 + tid] = ib3[tid]; }
    __syncthreads();

    phase0(smem, SB, hin, h, lane, w, tid);

    // reconvert slot0 <- W1a for level phases
    __syncthreads();
    conv_w8(smem, aw1, 128, 64, SW1H, SW1L, tid);
    grid_barrier(0);

    for (int lvl = 0; lvl < 7; lvl++) {
        const int* src = esrc  + (size_t)lvl * NPL * DEG;
        const int* msk = emask + (size_t)lvl * NPL * DEG;
        phase_level(smem, SB, h, src, msk, lvl, (lvl < 6) ? 1 : 0, lane, w, tid);
        if (lvl < 6) grid_barrier(1 + lvl);
    }
}

// ---------------------------------------------------------------------------
extern "C" void kernel_launch(void* const* d_in, const int* in_sizes, int n_in,
                              void* d_out, int out_size)
{
    (void)in_sizes; (void)n_in; (void)out_size;
    const float* h_in  = (const float*)d_in[0];
    const int*   esrc  = (const int*)d_in[1];
    const int*   emask = (const int*)d_in[2];
    const float* iw1 = (const float*)d_in[3];
    const float* ib1 = (const float*)d_in[4];
    const float* iw2 = (const float*)d_in[5];
    const float* ib2 = (const float*)d_in[6];
    const float* iw3 = (const float*)d_in[7];
    const float* ib3 = (const float*)d_in[8];
    const float* aw1 = (const float*)d_in[9];
    const float* ab1 = (const float*)d_in[10];
    const float* aw2 = (const float*)d_in[11];
    const float* ab2 = (const float*)d_in[12];
    const float* aw3 = (const float*)d_in[13];
    const float* ab3 = (const float*)d_in[14];

    float* h = (float*)d_out;

    static bool once = false;
    if (!once) {
        cudaFuncSetAttribute(persist_kernel, cudaFuncAttributeMaxDynamicSharedMemorySize, SM_TOTAL);
        once = true;
    }

    // single kernel launch: weight conversion, h level-0 copy, all 8 phases inside
    persist_kernel<<<GRIDSZ, NT, SM_TOTAL>>>(h_in, h, esrc, emask,
                                             aw1, ab1, aw2, ab2, aw3, ab3,
                                             iw1, ib1, iw2, ib2, iw3, ib3);
}